// round 13
// baseline (speedup 1.0000x reference)
#include <cuda_runtime.h>
#include <cuda_bf16.h>
#include <cstdint>

// ============================================================================
// DigitConvolutionalModel: conv folds into W1 -> pure 4-layer MLP
//   784 -> 200 -> 200 -> 200 -> 10, batch 65536, fp32 in/out.
// Single-pass TF32 (mma.sync.m16n8k8, fp32 accum), 26 MMAs/warp/chunk.
// THIS ROUND: warp grid 2M x 4N, perfectly balanced pair scheme:
//   each warp = 6 main j-tiles x both m16 tiles + ONE extra (j,mtile) pair
//   -> 13 pairs = 26 MMAs on every warp; W-fragment LDS drops 53->29 kB/chunk
//   (A rises 8->16 kB; net shared-port traffic -22%).
//   m-tiles processed sequentially with W held in regs -> ~105 regs, no spill.
// 3-deep cp.async ring, one __syncthreads per k-chunk, 2 CTAs/SM.
// ============================================================================

#define CTA_THREADS 256

#define NK1 49
#define NKH 13
#define NJH 26
#define NJO 2

// fragment-linear tf32 weights: uint4 per (ks, j, lane) =
//   {W[k0+t][n], W[k0+t+4][n], W[k0+8+t][n], W[k0+12+t][n]}  (tf32 bits)
//   where k0 = 16*ks, n = 8*j + (lane>>2), t = lane&3
__device__ uint4 g_Wb1[NK1 * NJH * 32];
__device__ uint4 g_Wb2[NKH * NJH * 32];
__device__ uint4 g_Wb3[NKH * NJH * 32];
__device__ uint4 g_Wb4[NKH * NJO * 32];

// ---------------------------------------------------------------------------
__device__ __forceinline__ uint32_t to_tf32(float f) {
    uint32_t r;
    asm("cvt.rna.tf32.f32 %0, %1;" : "=r"(r) : "f"(f));
    return r;
}

__device__ __forceinline__ void mma_tf32(float* c,
        uint32_t a0, uint32_t a1, uint32_t a2, uint32_t a3,
        uint32_t b0, uint32_t b1) {
    asm volatile(
        "mma.sync.aligned.m16n8k8.row.col.f32.tf32.tf32.f32 "
        "{%0,%1,%2,%3},{%4,%5,%6,%7},{%8,%9},{%0,%1,%2,%3};"
        : "+f"(c[0]), "+f"(c[1]), "+f"(c[2]), "+f"(c[3])
        : "r"(a0), "r"(a1), "r"(a2), "r"(a3), "r"(b0), "r"(b1));
}

__device__ __forceinline__ void cp16(void* dst_smem, const void* src) {
    uint32_t d = (uint32_t)__cvta_generic_to_shared(dst_smem);
    asm volatile("cp.async.cg.shared.global [%0], [%1], 16;" :: "r"(d), "l"(src));
}
#define CP_COMMIT asm volatile("cp.async.commit_group;" ::: "memory")
#define CP_WAIT1  asm volatile("cp.async.wait_group 1;" ::: "memory")

// ---------------------------------------------------------------------------
// prep kernel: fold conv into W1eff, tf32-round, fragment-linearize
// ---------------------------------------------------------------------------
__device__ __forceinline__ float w_l1(const float* cw, const float* W1, int k, int n) {
    if (n >= 200 || k >= 784) return 0.f;
    int r = k / 28, c = k % 28;
    float s = 0.f;
    #pragma unroll
    for (int dy = 0; dy < 3; ++dy) {
        int i = r - dy;
        if (i < 0 || i > 25) continue;
        #pragma unroll
        for (int dx = 0; dx < 3; ++dx) {
            int j = c - dx;
            if (j < 0 || j > 25) continue;
            s += cw[dy * 3 + dx] * W1[(i * 26 + j) * 200 + n];
        }
    }
    return s;
}

__global__ void prep_kernel(const float* __restrict__ cw,
                            const float* __restrict__ W1,
                            const float* __restrict__ W2,
                            const float* __restrict__ W3,
                            const float* __restrict__ W4) {
    int s = blockIdx.x * CTA_THREADS + threadIdx.x;
    const int E1 = NK1 * NJH * 32;
    const int E2 = E1 + NKH * NJH * 32;
    const int E3 = E2 + NKH * NJH * 32;
    const int E4 = E3 + NKH * NJO * 32;
    if (s >= E4) return;

    uint4* dst; int loc, nj, which;
    if (s < E1)      { dst = g_Wb1; loc = s;      nj = NJH; which = 1; }
    else if (s < E2) { dst = g_Wb2; loc = s - E1; nj = NJH; which = 2; }
    else if (s < E3) { dst = g_Wb3; loc = s - E2; nj = NJH; which = 3; }
    else             { dst = g_Wb4; loc = s - E3; nj = NJO; which = 4; }

    int lane = loc & 31;
    int j    = (loc >> 5) % nj;
    int ks   = loc / (nj * 32);
    int g = lane >> 2, t = lane & 3;
    int n  = 8 * j + g;
    int k0 = 16 * ks;
    int ka = k0 + t, kb = k0 + t + 4, kc = k0 + 8 + t, kd = k0 + 12 + t;

    float w0, w1, w2, w3;
    if (which == 1) {
        w0 = w_l1(cw, W1, ka, n);
        w1 = w_l1(cw, W1, kb, n);
        w2 = w_l1(cw, W1, kc, n);
        w3 = w_l1(cw, W1, kd, n);
    } else if (which == 4) {
        w0 = (ka < 200 && n < 10) ? W4[ka * 10 + n] : 0.f;
        w1 = (kb < 200 && n < 10) ? W4[kb * 10 + n] : 0.f;
        w2 = (kc < 200 && n < 10) ? W4[kc * 10 + n] : 0.f;
        w3 = (kd < 200 && n < 10) ? W4[kd * 10 + n] : 0.f;
    } else {
        const float* W = (which == 2) ? W2 : W3;
        w0 = (ka < 200 && n < 200) ? W[ka * 200 + n] : 0.f;
        w1 = (kb < 200 && n < 200) ? W[kb * 200 + n] : 0.f;
        w2 = (kc < 200 && n < 200) ? W[kc * 200 + n] : 0.f;
        w3 = (kd < 200 && n < 200) ? W[kd * 200 + n] : 0.f;
    }

    dst[loc] = make_uint4(to_tf32(w0), to_tf32(w1), to_tf32(w2), to_tf32(w3));
}

// ---------------------------------------------------------------------------
// main fused kernel (M = 64 rows per CTA, 3-deep ring, 1 barrier/chunk)
// SMEM (floats):
//   [0,3840)        xs: 3 x [64][20] fp32 x-stage (stride 20)
//   [3840,13824)    ws: 3 x [832] uint4 weight stage
//   [13824,27392)   hf: [64][212] tf32-rounded fp32 h (stride 212)
//   [27392,28032)   sb: biases b1[208] b2[208] b3[208] b4[16]
// ---------------------------------------------------------------------------
#define SMEM_BYTES 112128
#define HSTR 212

__global__ void __launch_bounds__(CTA_THREADS, 2)
mlp_kernel(const float* __restrict__ x,
           const float* __restrict__ b1, const float* __restrict__ b2,
           const float* __restrict__ b3, const float* __restrict__ b4,
           float* __restrict__ out) {
    extern __shared__ float smf[];
    float*    xs = smf;                               // 3 x 1280 floats
    uint4*    ws = (uint4*)(smf + 3840);              // 3 x 832 uint4
    uint32_t* hf = (uint32_t*)(smf + 13824);          // 64 x 212 tf32 bits
    float*    sb = smf + 27392;

    const int tid  = threadIdx.x;
    const int lane = tid & 31;
    const int warp = tid >> 5;
    const int g = lane >> 2, t = lane & 3;
    const int mh  = warp >> 2;                 // M-half: rows mh*32..mh*32+31
    const int nq  = warp & 3;                  // N-quarter
    const int jb  = 6 * nq;                    // main j-tiles [jb, jb+6)
    const int je  = 24 + (nq & 1);             // extra j-tile (24 or 25)
    const int emt = nq >> 1;                   // extra pair's mt (within half)
    const int r0  = blockIdx.x * 64;

    // biases (padded)
    if (tid < 208) {
        sb[tid]       = (tid < 200) ? b1[tid] : 0.f;
        sb[208 + tid] = (tid < 200) ? b2[tid] : 0.f;
        sb[416 + tid] = (tid < 200) ? b3[tid] : 0.f;
    }
    if (tid < 16) sb[624 + tid] = (tid < 10) ? b4[tid] : 0.f;

    float C[2][6][4];     // main: 2 m16 tiles x 6 j-tiles
    float CE[4];          // extra pair (je, 2mh+emt)

    // --------------------- helpers ---------------------
    auto stage_w = [&](const uint4* src, int count, int buf) {
        uint4* d = ws + buf * 832;
        for (int i = tid; i < count; i += CTA_THREADS) cp16(d + i, src + i);
    };
    auto stage_x = [&](int ks, int buf) {
        float* d = xs + buf * 1280;
        int row = tid >> 2, seg = tid & 3;
        cp16(d + row * 20 + seg * 4, x + (size_t)(r0 + row) * 784 + ks * 16 + seg * 4);
    };
    auto zeroC = [&]() {
        #pragma unroll
        for (int mt = 0; mt < 2; ++mt)
            #pragma unroll
            for (int j = 0; j < 6; ++j)
                #pragma unroll
                for (int q = 0; q < 4; ++q) C[mt][j][q] = 0.f;
        #pragma unroll
        for (int q = 0; q < 4; ++q) CE[q] = 0.f;
    };
    // store one (J, mtile) C-quad (bias+relu+tf32-round) into hf
    auto put_pair = [&](int J, int mtile, const float* c, const float* bias) {
        float2 bb = *(const float2*)(bias + 8 * J + 2 * t);
        float v0 = fmaxf(c[0] + bb.x, 0.f);
        float v1 = fmaxf(c[1] + bb.y, 0.f);
        float v2 = fmaxf(c[2] + bb.x, 0.f);
        float v3 = fmaxf(c[3] + bb.y, 0.f);
        int row = mtile * 16 + g;
        uint2 u0 = make_uint2(to_tf32(v0), to_tf32(v1));
        uint2 u1 = make_uint2(to_tf32(v2), to_tf32(v3));
        *(uint2*)(hf + row * HSTR + 8 * J + 2 * t)       = u0;
        *(uint2*)(hf + (row + 8) * HSTR + 8 * J + 2 * t) = u1;
    };
    auto store_h = [&](const float* bias) {
        #pragma unroll
        for (int mt = 0; mt < 2; ++mt)
            #pragma unroll
            for (int j = 0; j < 6; ++j)
                put_pair(jb + j, mh * 2 + mt, C[mt][j], bias);
        put_pair(je, mh * 2 + emt, CE, bias);
    };
    // A-fragment load for one m16 tile (conflict-free LDS.32)
    auto load_a_mt = [&](int ks, int mt, uint32_t a[8]) {
        int base = (mh * 32 + mt * 16 + g) * HSTR + 16 * ks + t;
        a[0] = hf[base];
        a[1] = hf[base + 8 * HSTR];
        a[2] = hf[base + 4];
        a[3] = hf[base + 4 + 8 * HSTR];
        a[4] = hf[base + 8];
        a[5] = hf[base + 8 + 8 * HSTR];
        a[6] = hf[base + 12];
        a[7] = hf[base + 12 + 8 * HSTR];
    };
    // 26 MMAs/warp: W held in regs across both m-tiles; A reloaded per tile
    auto mma_chunk = [&](const uint4* wl, const uint32_t a0[8], const uint32_t a1[8]) {
        uint4 w[6];
        #pragma unroll
        for (int i = 0; i < 6; ++i) w[i] = wl[(jb + i) * 32];
        uint4 we = wl[je * 32];
        const uint32_t* A[2] = { a0, a1 };
        #pragma unroll
        for (int mt = 0; mt < 2; ++mt) {
            const uint32_t* a = A[mt];
            #pragma unroll
            for (int i = 0; i < 6; ++i)
                mma_tf32(C[mt][i], a[0], a[1], a[2], a[3], w[i].x, w[i].y);
            #pragma unroll
            for (int i = 0; i < 6; ++i)
                mma_tf32(C[mt][i], a[4], a[5], a[6], a[7], w[i].z, w[i].w);
            if (emt == mt) {
                mma_tf32(CE, a[0], a[1], a[2], a[3], we.x, we.y);
                mma_tf32(CE, a[4], a[5], a[6], a[7], we.z, we.w);
            }
        }
    };

    // =========================== Layer 1 (K=784) ===========================
    zeroC();
    stage_x(0, 0); stage_w(g_Wb1, 832, 0); CP_COMMIT;
    stage_x(1, 1); stage_w(g_Wb1 + 832, 832, 1); CP_COMMIT;
    {
        int cur = 0, st = 2;
        for (int ks = 0; ks < NK1; ++ks) {
            CP_WAIT1;                      // group ks complete (ks+1 pending)
            __syncthreads();               // visibility + WAR for buf st
            if (ks + 2 < NK1) { stage_x(ks + 2, st); stage_w(g_Wb1 + (ks + 2) * 832, 832, st); }
            CP_COMMIT;

            uint32_t a0[8], a1[8];
            #pragma unroll
            for (int mt = 0; mt < 2; ++mt) {
                uint32_t* a = mt ? a1 : a0;
                const float* xb = xs + cur * 1280 + (mh * 32 + mt * 16 + g) * 20;
                a[0] = to_tf32(xb[t]);
                a[1] = to_tf32(xb[160 + t]);          // row+8
                a[2] = to_tf32(xb[t + 4]);
                a[3] = to_tf32(xb[160 + t + 4]);
                a[4] = to_tf32(xb[t + 8]);
                a[5] = to_tf32(xb[160 + t + 8]);
                a[6] = to_tf32(xb[t + 12]);
                a[7] = to_tf32(xb[160 + t + 12]);
            }
            mma_chunk(ws + cur * 832 + lane, a0, a1);
            if (++cur == 3) cur = 0;
            if (++st  == 3) st  = 0;
        }
    }
    __syncthreads();
    store_h(sb);
    __syncthreads();

    // ======================= Layers 2 & 3 (K=208) ==========================
    const uint4* Wmid[2] = { g_Wb2, g_Wb3 };
    for (int l = 0; l < 2; ++l) {
        zeroC();
        stage_w(Wmid[l], 832, 0); CP_COMMIT;
        stage_w(Wmid[l] + 832, 832, 1); CP_COMMIT;
        int cur = 0, st = 2;
        for (int ks = 0; ks < NKH; ++ks) {
            CP_WAIT1;
            __syncthreads();
            if (ks + 2 < NKH) stage_w(Wmid[l] + (ks + 2) * 832, 832, st);
            CP_COMMIT;

            uint32_t a0[8], a1[8];
            load_a_mt(ks, 0, a0);
            load_a_mt(ks, 1, a1);
            mma_chunk(ws + cur * 832 + lane, a0, a1);
            if (++cur == 3) cur = 0;
            if (++st  == 3) st  = 0;
        }
        __syncthreads();                 // all h reads done before overwrite
        store_h(sb + 208 * (l + 1));
        __syncthreads();
    }

    // =========================== Layer 4 (N=10) ============================
    // 2 n8-tiles x 4 m16-tiles = 8 (j,mtile) pairs -> exactly one per warp.
    float C4[4];
    #pragma unroll
    for (int q = 0; q < 4; ++q) C4[q] = 0.f;
    const int j4 = nq & 1;                 // this warp's n8 tile
    // this warp's m16 tile = mh*2 + emt

    stage_w(g_Wb4, 64, 0); CP_COMMIT;
    stage_w(g_Wb4 + 64, 64, 1); CP_COMMIT;
    {
        int cur = 0, st = 2;
        for (int ks = 0; ks < NKH; ++ks) {
            CP_WAIT1;
            __syncthreads();
            if (ks + 2 < NKH) stage_w(g_Wb4 + (ks + 2) * 64, 64, st);
            CP_COMMIT;

            uint32_t a[8];
            load_a_mt(ks, emt, a);
            uint4 w = ws[cur * 832 + j4 * 32 + lane];
            mma_tf32(C4, a[0], a[1], a[2], a[3], w.x, w.y);
            mma_tf32(C4, a[4], a[5], a[6], a[7], w.z, w.w);
            if (++cur == 3) cur = 0;
            if (++st  == 3) st  = 0;
        }
    }

    // output: warp covers m16 tile (2mh+emt), n8 tile j4; cols 8*j4+2t..+1
    {
        int col = 8 * j4 + 2 * t;
        if (col < 10) {
            float2 bb = *(const float2*)(sb + 624 + col);
            int rowg = r0 + mh * 32 + emt * 16 + g;
            float2 o0 = { C4[0] + bb.x, C4[1] + bb.y };
            float2 o1 = { C4[2] + bb.x, C4[3] + bb.y };
            *(float2*)(out + (size_t)rowg * 10 + col)       = o0;
            *(float2*)(out + (size_t)(rowg + 8) * 10 + col) = o1;
        }
    }
}

// ---------------------------------------------------------------------------
extern "C" void kernel_launch(void* const* d_in, const int* in_sizes, int n_in,
                              void* d_out, int out_size) {
    const float* x  = (const float*)d_in[0];
    const float* cw = (const float*)d_in[1];
    const float* W1 = (const float*)d_in[2];
    const float* b1 = (const float*)d_in[3];
    const float* W2 = (const float*)d_in[4];
    const float* b2 = (const float*)d_in[5];
    const float* W3 = (const float*)d_in[6];
    const float* b3 = (const float*)d_in[7];
    const float* W4 = (const float*)d_in[8];
    const float* b4 = (const float*)d_in[9];
    float* out = (float*)d_out;

    cudaFuncSetAttribute(mlp_kernel, cudaFuncAttributeMaxDynamicSharedMemorySize, SMEM_BYTES);

    prep_kernel<<<247, CTA_THREADS>>>(cw, W1, W2, W3, W4);
    mlp_kernel<<<1024, CTA_THREADS, SMEM_BYTES>>>(x, b1, b2, b3, b4, out);
}

// round 14
// speedup vs baseline: 1.0715x; 1.0715x over previous
#include <cuda_runtime.h>
#include <cuda_bf16.h>
#include <cstdint>

// ============================================================================
// DigitConvolutionalModel: conv folds into W1 -> pure 4-layer MLP
//   784 -> 200 -> 200 -> 200 -> 10, batch 65536, fp32 in/out.
// Single-pass TF32 (mma.sync.m16n8k8, fp32 accum). CTA = 64 rows, 256 thr,
// warps 4M x 2N, 13 j-tiles/warp, 26 MMAs/warp/chunk (== R12 best).
// THIS ROUND: group-double-buffered pipeline at 2-chunk granularity:
//   one wait_group(0) + one __syncthreads per PAIR of k16 chunks
//   -> sync points per CTA 88 -> 46; prefetch distance doubles.
//   Layer-1 x-stage ring ALIASED into the hf region (hf first written after
//   layer 1 ends) -> 4-slot W ring fits: SMEM 110.1 kB, still 2 CTAs/SM.
// ============================================================================

#define CTA_THREADS 256

#define NK1 49
#define NKH 13
#define NJH 26
#define NJO 2

// fragment-linear tf32 weights: uint4 per (ks, j, lane) =
//   {W[k0+t][n], W[k0+t+4][n], W[k0+8+t][n], W[k0+12+t][n]}  (tf32 bits)
//   where k0 = 16*ks, n = 8*j + (lane>>2), t = lane&3
__device__ uint4 g_Wb1[NK1 * NJH * 32];
__device__ uint4 g_Wb2[NKH * NJH * 32];
__device__ uint4 g_Wb3[NKH * NJH * 32];
__device__ uint4 g_Wb4[NKH * NJO * 32];

// ---------------------------------------------------------------------------
__device__ __forceinline__ uint32_t to_tf32(float f) {
    uint32_t r;
    asm("cvt.rna.tf32.f32 %0, %1;" : "=r"(r) : "f"(f));
    return r;
}

__device__ __forceinline__ void mma_tf32(float* c,
        uint32_t a0, uint32_t a1, uint32_t a2, uint32_t a3,
        uint32_t b0, uint32_t b1) {
    asm volatile(
        "mma.sync.aligned.m16n8k8.row.col.f32.tf32.tf32.f32 "
        "{%0,%1,%2,%3},{%4,%5,%6,%7},{%8,%9},{%0,%1,%2,%3};"
        : "+f"(c[0]), "+f"(c[1]), "+f"(c[2]), "+f"(c[3])
        : "r"(a0), "r"(a1), "r"(a2), "r"(a3), "r"(b0), "r"(b1));
}

__device__ __forceinline__ void cp16(void* dst_smem, const void* src) {
    uint32_t d = (uint32_t)__cvta_generic_to_shared(dst_smem);
    asm volatile("cp.async.cg.shared.global [%0], [%1], 16;" :: "r"(d), "l"(src));
}
#define CP_COMMIT asm volatile("cp.async.commit_group;" ::: "memory")
#define CP_WAIT0  asm volatile("cp.async.wait_group 0;" ::: "memory")

// ---------------------------------------------------------------------------
// prep kernel: fold conv into W1eff, tf32-round, fragment-linearize
// ---------------------------------------------------------------------------
__device__ __forceinline__ float w_l1(const float* cw, const float* W1, int k, int n) {
    if (n >= 200 || k >= 784) return 0.f;
    int r = k / 28, c = k % 28;
    float s = 0.f;
    #pragma unroll
    for (int dy = 0; dy < 3; ++dy) {
        int i = r - dy;
        if (i < 0 || i > 25) continue;
        #pragma unroll
        for (int dx = 0; dx < 3; ++dx) {
            int j = c - dx;
            if (j < 0 || j > 25) continue;
            s += cw[dy * 3 + dx] * W1[(i * 26 + j) * 200 + n];
        }
    }
    return s;
}

__global__ void prep_kernel(const float* __restrict__ cw,
                            const float* __restrict__ W1,
                            const float* __restrict__ W2,
                            const float* __restrict__ W3,
                            const float* __restrict__ W4) {
    int s = blockIdx.x * CTA_THREADS + threadIdx.x;
    const int E1 = NK1 * NJH * 32;
    const int E2 = E1 + NKH * NJH * 32;
    const int E3 = E2 + NKH * NJH * 32;
    const int E4 = E3 + NKH * NJO * 32;
    if (s >= E4) return;

    uint4* dst; int loc, nj, which;
    if (s < E1)      { dst = g_Wb1; loc = s;      nj = NJH; which = 1; }
    else if (s < E2) { dst = g_Wb2; loc = s - E1; nj = NJH; which = 2; }
    else if (s < E3) { dst = g_Wb3; loc = s - E2; nj = NJH; which = 3; }
    else             { dst = g_Wb4; loc = s - E3; nj = NJO; which = 4; }

    int lane = loc & 31;
    int j    = (loc >> 5) % nj;
    int ks   = loc / (nj * 32);
    int g = lane >> 2, t = lane & 3;
    int n  = 8 * j + g;
    int k0 = 16 * ks;
    int ka = k0 + t, kb = k0 + t + 4, kc = k0 + 8 + t, kd = k0 + 12 + t;

    float w0, w1, w2, w3;
    if (which == 1) {
        w0 = w_l1(cw, W1, ka, n);
        w1 = w_l1(cw, W1, kb, n);
        w2 = w_l1(cw, W1, kc, n);
        w3 = w_l1(cw, W1, kd, n);
    } else if (which == 4) {
        w0 = (ka < 200 && n < 10) ? W4[ka * 10 + n] : 0.f;
        w1 = (kb < 200 && n < 10) ? W4[kb * 10 + n] : 0.f;
        w2 = (kc < 200 && n < 10) ? W4[kc * 10 + n] : 0.f;
        w3 = (kd < 200 && n < 10) ? W4[kd * 10 + n] : 0.f;
    } else {
        const float* W = (which == 2) ? W2 : W3;
        w0 = (ka < 200 && n < 200) ? W[ka * 200 + n] : 0.f;
        w1 = (kb < 200 && n < 200) ? W[kb * 200 + n] : 0.f;
        w2 = (kc < 200 && n < 200) ? W[kc * 200 + n] : 0.f;
        w3 = (kd < 200 && n < 200) ? W[kd * 200 + n] : 0.f;
    }

    dst[loc] = make_uint4(to_tf32(w0), to_tf32(w1), to_tf32(w2), to_tf32(w3));
}

// ---------------------------------------------------------------------------
// main fused kernel (M = 64 rows per CTA, 2-chunk group double buffer)
// SMEM (floats):
//   [0,13312)       ws: 4 x [832] uint4 weight slots (53,248 B)
//   [13312,26880)   hf: [64][212] tf32-rounded fp32 h (54,272 B)
//                     (layer-1 xs ring 4 x [64][20] fp32 ALIASED at hf base;
//                      hf is first written after layer 1's final barrier)
//   [26880,27520)   sb: biases b1[208] b2[208] b3[208] b4[16]
// ---------------------------------------------------------------------------
#define SMEM_BYTES 110080
#define HSTR 212

__global__ void __launch_bounds__(CTA_THREADS, 2)
mlp_kernel(const float* __restrict__ x,
           const float* __restrict__ b1, const float* __restrict__ b2,
           const float* __restrict__ b3, const float* __restrict__ b4,
           float* __restrict__ out) {
    extern __shared__ float smf[];
    uint4*    ws = (uint4*)smf;                       // 4 x 832 uint4
    uint32_t* hf = (uint32_t*)(smf + 13312);          // 64 x 212 tf32 bits
    float*    xs = smf + 13312;                       // ALIAS: 4 x 1280 floats
    float*    sb = smf + 26880;

    const int tid  = threadIdx.x;
    const int lane = tid & 31;
    const int warp = tid >> 5;
    const int g = lane >> 2, t = lane & 3;
    const int mq = warp >> 1;       // M-quarter 0..3 (16 rows each)
    const int nh = warp & 1;        // N-half
    const int r0 = blockIdx.x * 64;

    // biases (padded)
    if (tid < 208) {
        sb[tid]       = (tid < 200) ? b1[tid] : 0.f;
        sb[208 + tid] = (tid < 200) ? b2[tid] : 0.f;
        sb[416 + tid] = (tid < 200) ? b3[tid] : 0.f;
    }
    if (tid < 16) sb[624 + tid] = (tid < 10) ? b4[tid] : 0.f;

    float C[13][4];

    // --------------------- helpers ---------------------
    auto stage_w = [&](const uint4* src, int count, int slot) {
        uint4* d = ws + slot * 832;
        for (int i = tid; i < count; i += CTA_THREADS) cp16(d + i, src + i);
    };
    auto stage_x = [&](int ks, int slot) {
        float* d = xs + slot * 1280;
        int row = tid >> 2, seg = tid & 3;
        cp16(d + row * 20 + seg * 4, x + (size_t)(r0 + row) * 784 + ks * 16 + seg * 4);
    };
    auto zeroC = [&]() {
        #pragma unroll
        for (int j = 0; j < 13; ++j)
            #pragma unroll
            for (int q = 0; q < 4; ++q) C[j][q] = 0.f;
    };
    // h producer: tf32-rounded fp32, row-major stride 212
    auto store_h = [&](const float* bias) {
        int row = mq * 16 + g;
        #pragma unroll
        for (int j = 0; j < 13; ++j) {
            int J = 13 * nh + j;
            float2 bb = *(const float2*)(bias + 8 * J + 2 * t);
            float v0 = fmaxf(C[j][0] + bb.x, 0.f);
            float v1 = fmaxf(C[j][1] + bb.y, 0.f);
            float v2 = fmaxf(C[j][2] + bb.x, 0.f);
            float v3 = fmaxf(C[j][3] + bb.y, 0.f);
            uint2 u0 = make_uint2(to_tf32(v0), to_tf32(v1));
            uint2 u1 = make_uint2(to_tf32(v2), to_tf32(v3));
            *(uint2*)(hf + row * HSTR + 8 * J + 2 * t)       = u0;
            *(uint2*)(hf + (row + 8) * HSTR + 8 * J + 2 * t) = u1;
        }
    };
    // consumer: direct tf32 A-fragment loads (conflict-free LDS.32)
    auto load_a_h = [&](int ks, uint32_t a[8]) {
        int base = (mq * 16 + g) * HSTR + 16 * ks + t;
        a[0] = hf[base];
        a[1] = hf[base + 8 * HSTR];
        a[2] = hf[base + 4];
        a[3] = hf[base + 4 + 8 * HSTR];
        a[4] = hf[base + 8];
        a[5] = hf[base + 8 + 8 * HSTR];
        a[6] = hf[base + 12];
        a[7] = hf[base + 12 + 8 * HSTR];
    };
    auto load_a_x = [&](int slot, uint32_t a[8]) {
        const float* xb = xs + slot * 1280 + (mq * 16 + g) * 20;
        a[0] = to_tf32(xb[t]);
        a[1] = to_tf32(xb[160 + t]);          // row+8
        a[2] = to_tf32(xb[t + 4]);
        a[3] = to_tf32(xb[160 + t + 4]);
        a[4] = to_tf32(xb[t + 8]);
        a[5] = to_tf32(xb[160 + t + 8]);
        a[6] = to_tf32(xb[t + 12]);
        a[7] = to_tf32(xb[160 + t + 12]);
    };
    // 26 MMAs (13 j x 2 k8-steps), grouped {5,4,4}, step-major in group
    auto mma_train = [&](const uint4* wb, const uint32_t a[8]) {
        {   // j = 0..4
            uint4 w[5];
            #pragma unroll
            for (int i = 0; i < 5; ++i) w[i] = wb[i * 32];
            #pragma unroll
            for (int i = 0; i < 5; ++i) mma_tf32(C[i], a[0], a[1], a[2], a[3], w[i].x, w[i].y);
            #pragma unroll
            for (int i = 0; i < 5; ++i) mma_tf32(C[i], a[4], a[5], a[6], a[7], w[i].z, w[i].w);
        }
        {   // j = 5..8
            uint4 w[4];
            #pragma unroll
            for (int i = 0; i < 4; ++i) w[i] = wb[(5 + i) * 32];
            #pragma unroll
            for (int i = 0; i < 4; ++i) mma_tf32(C[5 + i], a[0], a[1], a[2], a[3], w[i].x, w[i].y);
            #pragma unroll
            for (int i = 0; i < 4; ++i) mma_tf32(C[5 + i], a[4], a[5], a[6], a[7], w[i].z, w[i].w);
        }
        {   // j = 9..12
            uint4 w[4];
            #pragma unroll
            for (int i = 0; i < 4; ++i) w[i] = wb[(9 + i) * 32];
            #pragma unroll
            for (int i = 0; i < 4; ++i) mma_tf32(C[9 + i], a[0], a[1], a[2], a[3], w[i].x, w[i].y);
            #pragma unroll
            for (int i = 0; i < 4; ++i) mma_tf32(C[9 + i], a[4], a[5], a[6], a[7], w[i].z, w[i].w);
        }
    };

    // =========================== Layer 1 (K=784) ===========================
    // Group g = chunks {2g, 2g+1} in slots {(g&1)*2, (g&1)*2+1}.
    // One wait_group(0) + one __syncthreads per group.
    zeroC();
    stage_x(0, 0); stage_w(g_Wb1, 832, 0);
    stage_x(1, 1); stage_w(g_Wb1 + 832, 832, 1);
    CP_COMMIT;
    for (int gI = 0; gI < 25; ++gI) {
        CP_WAIT0;                          // group gI data arrived (this thread)
        __syncthreads();                   // CTA-wide visibility + WAR for next slots
        int nbase = ((gI + 1) & 1) * 2;
        int c0 = 2 * gI + 2, c1 = c0 + 1;
        if (c0 < NK1) { stage_x(c0, nbase);     stage_w(g_Wb1 + c0 * 832, 832, nbase); }
        if (c1 < NK1) { stage_x(c1, nbase + 1); stage_w(g_Wb1 + c1 * 832, 832, nbase + 1); }
        CP_COMMIT;

        int s0 = (gI & 1) * 2;
        {
            uint32_t a[8];
            load_a_x(s0, a);
            mma_train(ws + s0 * 832 + nh * 13 * 32 + lane, a);
        }
        if (2 * gI + 1 < NK1) {
            uint32_t a[8];
            load_a_x(s0 + 1, a);
            mma_train(ws + (s0 + 1) * 832 + nh * 13 * 32 + lane, a);
        }
    }
    __syncthreads();                       // xs dead from here; hf may be written
    store_h(sb);
    __syncthreads();

    // ======================= Layers 2 & 3 (K=208, 7 groups) ================
    const uint4* Wmid[2] = { g_Wb2, g_Wb3 };
    for (int l = 0; l < 2; ++l) {
        zeroC();
        stage_w(Wmid[l], 832, 0);
        stage_w(Wmid[l] + 832, 832, 1);
        CP_COMMIT;
        for (int gI = 0; gI < 7; ++gI) {
            CP_WAIT0;
            __syncthreads();
            int nbase = ((gI + 1) & 1) * 2;
            int c0 = 2 * gI + 2, c1 = c0 + 1;
            if (c0 < NKH) stage_w(Wmid[l] + c0 * 832, 832, nbase);
            if (c1 < NKH) stage_w(Wmid[l] + c1 * 832, 832, nbase + 1);
            CP_COMMIT;

            int s0 = (gI & 1) * 2;
            {
                uint32_t a[8];
                load_a_h(2 * gI, a);
                mma_train(ws + s0 * 832 + nh * 13 * 32 + lane, a);
            }
            if (2 * gI + 1 < NKH) {
                uint32_t a[8];
                load_a_h(2 * gI + 1, a);
                mma_train(ws + (s0 + 1) * 832 + nh * 13 * 32 + lane, a);
            }
        }
        __syncthreads();                 // all h reads done before overwrite
        store_h(sb + 208 * (l + 1));
        __syncthreads();
    }

    // =========================== Layer 4 (N=10, 7 groups) ==================
    float C4[4];
    #pragma unroll
    for (int q = 0; q < 4; ++q) C4[q] = 0.f;

    stage_w(g_Wb4, 64, 0);
    stage_w(g_Wb4 + 64, 64, 1);
    CP_COMMIT;
    for (int gI = 0; gI < 7; ++gI) {
        CP_WAIT0;
        __syncthreads();
        int nbase = ((gI + 1) & 1) * 2;
        int c0 = 2 * gI + 2, c1 = c0 + 1;
        if (c0 < NKH) stage_w(g_Wb4 + c0 * 64, 64, nbase);
        if (c1 < NKH) stage_w(g_Wb4 + c1 * 64, 64, nbase + 1);
        CP_COMMIT;

        int s0 = (gI & 1) * 2;
        {
            uint32_t a[8];
            load_a_h(2 * gI, a);
            uint4 w = ws[s0 * 832 + nh * 32 + lane];
            mma_tf32(C4, a[0], a[1], a[2], a[3], w.x, w.y);
            mma_tf32(C4, a[4], a[5], a[6], a[7], w.z, w.w);
        }
        if (2 * gI + 1 < NKH) {
            uint32_t a[8];
            load_a_h(2 * gI + 1, a);
            uint4 w = ws[(s0 + 1) * 832 + nh * 32 + lane];
            mma_tf32(C4, a[0], a[1], a[2], a[3], w.x, w.y);
            mma_tf32(C4, a[4], a[5], a[6], a[7], w.z, w.w);
        }
    }

    // output: cols 0..9 (tile nh*8 + 2t; guard padded cols)
    if (nh == 0 || t == 0) {
        int col = 8 * nh + 2 * t;
        float2 bb = *(const float2*)(sb + 624 + col);
        int rowg = r0 + mq * 16 + g;
        float2 o0 = { C4[0] + bb.x, C4[1] + bb.y };
        float2 o1 = { C4[2] + bb.x, C4[3] + bb.y };
        *(float2*)(out + (size_t)rowg * 10 + col)       = o0;
        *(float2*)(out + (size_t)(rowg + 8) * 10 + col) = o1;
    }
}

// ---------------------------------------------------------------------------
extern "C" void kernel_launch(void* const* d_in, const int* in_sizes, int n_in,
                              void* d_out, int out_size) {
    const float* x  = (const float*)d_in[0];
    const float* cw = (const float*)d_in[1];
    const float* W1 = (const float*)d_in[2];
    const float* b1 = (const float*)d_in[3];
    const float* W2 = (const float*)d_in[4];
    const float* b2 = (const float*)d_in[5];
    const float* W3 = (const float*)d_in[6];
    const float* b3 = (const float*)d_in[7];
    const float* W4 = (const float*)d_in[8];
    const float* b4 = (const float*)d_in[9];
    float* out = (float*)d_out;

    cudaFuncSetAttribute(mlp_kernel, cudaFuncAttributeMaxDynamicSharedMemorySize, SMEM_BYTES);

    prep_kernel<<<247, CTA_THREADS>>>(cw, W1, W2, W3, W4);
    mlp_kernel<<<1024, CTA_THREADS, SMEM_BYTES>>>(x, b1, b2, b3, b4, out);
}

// round 16
// speedup vs baseline: 1.0844x; 1.0121x over previous
#include <cuda_runtime.h>
#include <cuda_bf16.h>
#include <cstdint>

// ============================================================================
// DigitConvolutionalModel: conv folds into W1 -> pure 4-layer MLP
//   784 -> 200 -> 200 -> 200 -> 10, batch 65536, fp32 in/out.
// Single-pass TF32 (mma.sync.m16n8k8, fp32 accum). CTA = 64 rows, 256 thr,
// warps 4M x 2N, 13 j-tiles/warp, 26 MMAs/warp/chunk.
// Group-double-buffered pipeline (2 chunks/group), 46 sync points/CTA,
// layer-1 x ring aliased into hf. 2 CTAs/SM.                     (== R14)
// THIS ROUND (scheduling only):
//   1. mma asm is NOT volatile -> ptxas may software-pipeline LDS<->HMMA.
//   2. A-fragment loads hoisted ABOVE the cp.async wait + barrier in
//      layers 2/3/4 (hf is layer-stable) -> LDS latency overlaps the stall.
// ============================================================================

#define CTA_THREADS 256

#define NK1 49
#define NKH 13
#define NJH 26
#define NJO 2

// fragment-linear tf32 weights: uint4 per (ks, j, lane) =
//   {W[k0+t][n], W[k0+t+4][n], W[k0+8+t][n], W[k0+12+t][n]}  (tf32 bits)
//   where k0 = 16*ks, n = 8*j + (lane>>2), t = lane&3
__device__ uint4 g_Wb1[NK1 * NJH * 32];
__device__ uint4 g_Wb2[NKH * NJH * 32];
__device__ uint4 g_Wb3[NKH * NJH * 32];
__device__ uint4 g_Wb4[NKH * NJO * 32];

// ---------------------------------------------------------------------------
__device__ __forceinline__ uint32_t to_tf32(float f) {
    uint32_t r;
    asm("cvt.rna.tf32.f32 %0, %1;" : "=r"(r) : "f"(f));
    return r;
}

// NOT volatile: outputs are always consumed; lets ptxas schedule freely.
__device__ __forceinline__ void mma_tf32(float* c,
        uint32_t a0, uint32_t a1, uint32_t a2, uint32_t a3,
        uint32_t b0, uint32_t b1) {
    asm("mma.sync.aligned.m16n8k8.row.col.f32.tf32.tf32.f32 "
        "{%0,%1,%2,%3},{%4,%5,%6,%7},{%8,%9},{%0,%1,%2,%3};"
        : "+f"(c[0]), "+f"(c[1]), "+f"(c[2]), "+f"(c[3])
        : "r"(a0), "r"(a1), "r"(a2), "r"(a3), "r"(b0), "r"(b1));
}

__device__ __forceinline__ void cp16(void* dst_smem, const void* src) {
    uint32_t d = (uint32_t)__cvta_generic_to_shared(dst_smem);
    asm volatile("cp.async.cg.shared.global [%0], [%1], 16;" :: "r"(d), "l"(src));
}
#define CP_COMMIT asm volatile("cp.async.commit_group;" ::: "memory")
#define CP_WAIT0  asm volatile("cp.async.wait_group 0;" ::: "memory")

// ---------------------------------------------------------------------------
// prep kernel: fold conv into W1eff, tf32-round, fragment-linearize
// ---------------------------------------------------------------------------
__device__ __forceinline__ float w_l1(const float* cw, const float* W1, int k, int n) {
    if (n >= 200 || k >= 784) return 0.f;
    int r = k / 28, c = k % 28;
    float s = 0.f;
    #pragma unroll
    for (int dy = 0; dy < 3; ++dy) {
        int i = r - dy;
        if (i < 0 || i > 25) continue;
        #pragma unroll
        for (int dx = 0; dx < 3; ++dx) {
            int j = c - dx;
            if (j < 0 || j > 25) continue;
            s += cw[dy * 3 + dx] * W1[(i * 26 + j) * 200 + n];
        }
    }
    return s;
}

__global__ void prep_kernel(const float* __restrict__ cw,
                            const float* __restrict__ W1,
                            const float* __restrict__ W2,
                            const float* __restrict__ W3,
                            const float* __restrict__ W4) {
    int s = blockIdx.x * CTA_THREADS + threadIdx.x;
    const int E1 = NK1 * NJH * 32;
    const int E2 = E1 + NKH * NJH * 32;
    const int E3 = E2 + NKH * NJH * 32;
    const int E4 = E3 + NKH * NJO * 32;
    if (s >= E4) return;

    uint4* dst; int loc, nj, which;
    if (s < E1)      { dst = g_Wb1; loc = s;      nj = NJH; which = 1; }
    else if (s < E2) { dst = g_Wb2; loc = s - E1; nj = NJH; which = 2; }
    else if (s < E3) { dst = g_Wb3; loc = s - E2; nj = NJH; which = 3; }
    else             { dst = g_Wb4; loc = s - E3; nj = NJO; which = 4; }

    int lane = loc & 31;
    int j    = (loc >> 5) % nj;
    int ks   = loc / (nj * 32);
    int g = lane >> 2, t = lane & 3;
    int n  = 8 * j + g;
    int k0 = 16 * ks;
    int ka = k0 + t, kb = k0 + t + 4, kc = k0 + 8 + t, kd = k0 + 12 + t;

    float w0, w1, w2, w3;
    if (which == 1) {
        w0 = w_l1(cw, W1, ka, n);
        w1 = w_l1(cw, W1, kb, n);
        w2 = w_l1(cw, W1, kc, n);
        w3 = w_l1(cw, W1, kd, n);
    } else if (which == 4) {
        w0 = (ka < 200 && n < 10) ? W4[ka * 10 + n] : 0.f;
        w1 = (kb < 200 && n < 10) ? W4[kb * 10 + n] : 0.f;
        w2 = (kc < 200 && n < 10) ? W4[kc * 10 + n] : 0.f;
        w3 = (kd < 200 && n < 10) ? W4[kd * 10 + n] : 0.f;
    } else {
        const float* W = (which == 2) ? W2 : W3;
        w0 = (ka < 200 && n < 200) ? W[ka * 200 + n] : 0.f;
        w1 = (kb < 200 && n < 200) ? W[kb * 200 + n] : 0.f;
        w2 = (kc < 200 && n < 200) ? W[kc * 200 + n] : 0.f;
        w3 = (kd < 200 && n < 200) ? W[kd * 200 + n] : 0.f;
    }

    dst[loc] = make_uint4(to_tf32(w0), to_tf32(w1), to_tf32(w2), to_tf32(w3));
}

// ---------------------------------------------------------------------------
// main fused kernel (M = 64 rows per CTA, 2-chunk group double buffer)
// SMEM (floats):
//   [0,13312)       ws: 4 x [832] uint4 weight slots (53,248 B)
//   [13312,26880)   hf: [64][212] tf32-rounded fp32 h (54,272 B)
//                     (layer-1 xs ring 4 x [64][20] fp32 ALIASED at hf base)
//   [26880,27520)   sb: biases b1[208] b2[208] b3[208] b4[16]
// ---------------------------------------------------------------------------
#define SMEM_BYTES 110080
#define HSTR 212

__global__ void __launch_bounds__(CTA_THREADS, 2)
mlp_kernel(const float* __restrict__ x,
           const float* __restrict__ b1, const float* __restrict__ b2,
           const float* __restrict__ b3, const float* __restrict__ b4,
           float* __restrict__ out) {
    extern __shared__ float smf[];
    uint4*    ws = (uint4*)smf;                       // 4 x 832 uint4
    uint32_t* hf = (uint32_t*)(smf + 13312);          // 64 x 212 tf32 bits
    float*    xs = smf + 13312;                       // ALIAS: 4 x 1280 floats
    float*    sb = smf + 26880;

    const int tid  = threadIdx.x;
    const int lane = tid & 31;
    const int warp = tid >> 5;
    const int g = lane >> 2, t = lane & 3;
    const int mq = warp >> 1;       // M-quarter 0..3 (16 rows each)
    const int nh = warp & 1;        // N-half
    const int r0 = blockIdx.x * 64;

    // biases (padded)
    if (tid < 208) {
        sb[tid]       = (tid < 200) ? b1[tid] : 0.f;
        sb[208 + tid] = (tid < 200) ? b2[tid] : 0.f;
        sb[416 + tid] = (tid < 200) ? b3[tid] : 0.f;
    }
    if (tid < 16) sb[624 + tid] = (tid < 10) ? b4[tid] : 0.f;

    float C[13][4];

    // --------------------- helpers ---------------------
    auto stage_w = [&](const uint4* src, int count, int slot) {
        uint4* d = ws + slot * 832;
        for (int i = tid; i < count; i += CTA_THREADS) cp16(d + i, src + i);
    };
    auto stage_x = [&](int ks, int slot) {
        float* d = xs + slot * 1280;
        int row = tid >> 2, seg = tid & 3;
        cp16(d + row * 20 + seg * 4, x + (size_t)(r0 + row) * 784 + ks * 16 + seg * 4);
    };
    auto zeroC = [&]() {
        #pragma unroll
        for (int j = 0; j < 13; ++j)
            #pragma unroll
            for (int q = 0; q < 4; ++q) C[j][q] = 0.f;
    };
    // h producer: tf32-rounded fp32, row-major stride 212
    auto store_h = [&](const float* bias) {
        int row = mq * 16 + g;
        #pragma unroll
        for (int j = 0; j < 13; ++j) {
            int J = 13 * nh + j;
            float2 bb = *(const float2*)(bias + 8 * J + 2 * t);
            float v0 = fmaxf(C[j][0] + bb.x, 0.f);
            float v1 = fmaxf(C[j][1] + bb.y, 0.f);
            float v2 = fmaxf(C[j][2] + bb.x, 0.f);
            float v3 = fmaxf(C[j][3] + bb.y, 0.f);
            uint2 u0 = make_uint2(to_tf32(v0), to_tf32(v1));
            uint2 u1 = make_uint2(to_tf32(v2), to_tf32(v3));
            *(uint2*)(hf + row * HSTR + 8 * J + 2 * t)       = u0;
            *(uint2*)(hf + (row + 8) * HSTR + 8 * J + 2 * t) = u1;
        }
    };
    // consumer: direct tf32 A-fragment loads (conflict-free LDS.32)
    auto load_a_h = [&](int ks, uint32_t a[8]) {
        int base = (mq * 16 + g) * HSTR + 16 * ks + t;
        a[0] = hf[base];
        a[1] = hf[base + 8 * HSTR];
        a[2] = hf[base + 4];
        a[3] = hf[base + 4 + 8 * HSTR];
        a[4] = hf[base + 8];
        a[5] = hf[base + 8 + 8 * HSTR];
        a[6] = hf[base + 12];
        a[7] = hf[base + 12 + 8 * HSTR];
    };
    auto load_a_x = [&](int slot, uint32_t a[8]) {
        const float* xb = xs + slot * 1280 + (mq * 16 + g) * 20;
        a[0] = to_tf32(xb[t]);
        a[1] = to_tf32(xb[160 + t]);          // row+8
        a[2] = to_tf32(xb[t + 4]);
        a[3] = to_tf32(xb[160 + t + 4]);
        a[4] = to_tf32(xb[t + 8]);
        a[5] = to_tf32(xb[160 + t + 8]);
        a[6] = to_tf32(xb[t + 12]);
        a[7] = to_tf32(xb[160 + t + 12]);
    };
    // 26 MMAs (13 j x 2 k8-steps), grouped {5,4,4}, step-major in group
    auto mma_train = [&](const uint4* wb, const uint32_t a[8]) {
        {   // j = 0..4
            uint4 w[5];
            #pragma unroll
            for (int i = 0; i < 5; ++i) w[i] = wb[i * 32];
            #pragma unroll
            for (int i = 0; i < 5; ++i) mma_tf32(C[i], a[0], a[1], a[2], a[3], w[i].x, w[i].y);
            #pragma unroll
            for (int i = 0; i < 5; ++i) mma_tf32(C[i], a[4], a[5], a[6], a[7], w[i].z, w[i].w);
        }
        {   // j = 5..8
            uint4 w[4];
            #pragma unroll
            for (int i = 0; i < 4; ++i) w[i] = wb[(5 + i) * 32];
            #pragma unroll
            for (int i = 0; i < 4; ++i) mma_tf32(C[5 + i], a[0], a[1], a[2], a[3], w[i].x, w[i].y);
            #pragma unroll
            for (int i = 0; i < 4; ++i) mma_tf32(C[5 + i], a[4], a[5], a[6], a[7], w[i].z, w[i].w);
        }
        {   // j = 9..12
            uint4 w[4];
            #pragma unroll
            for (int i = 0; i < 4; ++i) w[i] = wb[(9 + i) * 32];
            #pragma unroll
            for (int i = 0; i < 4; ++i) mma_tf32(C[9 + i], a[0], a[1], a[2], a[3], w[i].x, w[i].y);
            #pragma unroll
            for (int i = 0; i < 4; ++i) mma_tf32(C[9 + i], a[4], a[5], a[6], a[7], w[i].z, w[i].w);
        }
    };

    // =========================== Layer 1 (K=784) ===========================
    // Group g = chunks {2g, 2g+1} in slots {(g&1)*2, (g&1)*2+1}.
    zeroC();
    stage_x(0, 0); stage_w(g_Wb1, 832, 0);
    stage_x(1, 1); stage_w(g_Wb1 + 832, 832, 1);
    CP_COMMIT;
    for (int gI = 0; gI < 25; ++gI) {
        CP_WAIT0;                          // group gI data arrived (this thread)
        __syncthreads();                   // CTA-wide visibility + WAR for next slots
        int nbase = ((gI + 1) & 1) * 2;
        int c0 = 2 * gI + 2, c1 = c0 + 1;
        if (c0 < NK1) { stage_x(c0, nbase);     stage_w(g_Wb1 + c0 * 832, 832, nbase); }
        if (c1 < NK1) { stage_x(c1, nbase + 1); stage_w(g_Wb1 + c1 * 832, 832, nbase + 1); }
        CP_COMMIT;

        int s0 = (gI & 1) * 2;
        {
            uint32_t a[8];
            load_a_x(s0, a);
            mma_train(ws + s0 * 832 + nh * 13 * 32 + lane, a);
        }
        if (2 * gI + 1 < NK1) {
            uint32_t a[8];
            load_a_x(s0 + 1, a);
            mma_train(ws + (s0 + 1) * 832 + nh * 13 * 32 + lane, a);
        }
    }
    __syncthreads();                       // xs dead from here; hf may be written
    store_h(sb);
    __syncthreads();

    // ======================= Layers 2 & 3 (K=208, 7 groups) ================
    const uint4* Wmid[2] = { g_Wb2, g_Wb3 };
    for (int l = 0; l < 2; ++l) {
        zeroC();
        stage_w(Wmid[l], 832, 0);
        stage_w(Wmid[l] + 832, 832, 1);
        CP_COMMIT;
        for (int gI = 0; gI < 7; ++gI) {
            // A-loads hoisted ABOVE the wait: hf is layer-stable, so these
            // LDS overlap the cp.async drain + barrier.
            uint32_t a0[8], a1[8];
            load_a_h(2 * gI, a0);
            bool has2 = (2 * gI + 1 < NKH);
            if (has2) load_a_h(2 * gI + 1, a1);

            CP_WAIT0;
            __syncthreads();
            int nbase = ((gI + 1) & 1) * 2;
            int c0 = 2 * gI + 2, c1 = c0 + 1;
            if (c0 < NKH) stage_w(Wmid[l] + c0 * 832, 832, nbase);
            if (c1 < NKH) stage_w(Wmid[l] + c1 * 832, 832, nbase + 1);
            CP_COMMIT;

            int s0 = (gI & 1) * 2;
            mma_train(ws + s0 * 832 + nh * 13 * 32 + lane, a0);
            if (has2)
                mma_train(ws + (s0 + 1) * 832 + nh * 13 * 32 + lane, a1);
        }
        __syncthreads();                 // all h reads done before overwrite
        store_h(sb + 208 * (l + 1));
        __syncthreads();
    }

    // =========================== Layer 4 (N=10, 7 groups) ==================
    float C4[4];
    #pragma unroll
    for (int q = 0; q < 4; ++q) C4[q] = 0.f;

    stage_w(g_Wb4, 64, 0);
    stage_w(g_Wb4 + 64, 64, 1);
    CP_COMMIT;
    for (int gI = 0; gI < 7; ++gI) {
        uint32_t a0[8], a1[8];
        load_a_h(2 * gI, a0);
        bool has2 = (2 * gI + 1 < NKH);
        if (has2) load_a_h(2 * gI + 1, a1);

        CP_WAIT0;
        __syncthreads();
        int nbase = ((gI + 1) & 1) * 2;
        int c0 = 2 * gI + 2, c1 = c0 + 1;
        if (c0 < NKH) stage_w(g_Wb4 + c0 * 64, 64, nbase);
        if (c1 < NKH) stage_w(g_Wb4 + c1 * 64, 64, nbase + 1);
        CP_COMMIT;

        int s0 = (gI & 1) * 2;
        {
            uint4 w = ws[s0 * 832 + nh * 32 + lane];
            mma_tf32(C4, a0[0], a0[1], a0[2], a0[3], w.x, w.y);
            mma_tf32(C4, a0[4], a0[5], a0[6], a0[7], w.z, w.w);
        }
        if (has2) {
            uint4 w = ws[(s0 + 1) * 832 + nh * 32 + lane];
            mma_tf32(C4, a1[0], a1[1], a1[2], a1[3], w.x, w.y);
            mma_tf32(C4, a1[4], a1[5], a1[6], a1[7], w.z, w.w);
        }
    }

    // output: cols 0..9 (tile nh*8 + 2t; guard padded cols)
    if (nh == 0 || t == 0) {
        int col = 8 * nh + 2 * t;
        float2 bb = *(const float2*)(sb + 624 + col);
        int rowg = r0 + mq * 16 + g;
        float2 o0 = { C4[0] + bb.x, C4[1] + bb.y };
        float2 o1 = { C4[2] + bb.x, C4[3] + bb.y };
        *(float2*)(out + (size_t)rowg * 10 + col)       = o0;
        *(float2*)(out + (size_t)(rowg + 8) * 10 + col) = o1;
    }
}

// ---------------------------------------------------------------------------
extern "C" void kernel_launch(void* const* d_in, const int* in_sizes, int n_in,
                              void* d_out, int out_size) {
    const float* x  = (const float*)d_in[0];
    const float* cw = (const float*)d_in[1];
    const float* W1 = (const float*)d_in[2];
    const float* b1 = (const float*)d_in[3];
    const float* W2 = (const float*)d_in[4];
    const float* b2 = (const float*)d_in[5];
    const float* W3 = (const float*)d_in[6];
    const float* b3 = (const float*)d_in[7];
    const float* W4 = (const float*)d_in[8];
    const float* b4 = (const float*)d_in[9];
    float* out = (float*)d_out;

    cudaFuncSetAttribute(mlp_kernel, cudaFuncAttributeMaxDynamicSharedMemorySize, SMEM_BYTES);

    prep_kernel<<<247, CTA_THREADS>>>(cw, W1, W2, W3, W4);
    mlp_kernel<<<1024, CTA_THREADS, SMEM_BYTES>>>(x, b1, b2, b3, b4, out);
}